// round 2
// baseline (speedup 1.0000x reference)
#include <cuda_runtime.h>
#include <cuda_bf16.h>
#include <cstdint>

#define N_NODES 100000
#define N_EDGES 1600000
#define FDIM    128
#define HEADS   8
#define EPS_F   1e-12f
#define ALPHA_F 0.2f

// Scratch (static device globals — no runtime allocation).
// g_sc[n*16 + h]  : h<8 -> s_src[n][h], h>=8 -> s_dst[n][h-8]   (6.4 MB, L2-resident)
// g_ssum[n*8 + h] : per-(node,head) sum of exp(e); inverted in-place by inv_kernel
__device__ __align__(16) float g_sc[N_NODES * 16];
__device__ __align__(16) float g_ssum[N_NODES * 8];

// ---------------------------------------------------------------------------
// Kernel 1: per-node scores. One warp per node (grid-stride loop).
// aa lives in 64 registers per lane (lane owns features 4*lane..4*lane+3 of
// all 16 projection rows). Reduction uses value-splitting: 16 partial sums
// across 32 lanes are reduced with only 16 shuffles (8+4+2+1+1) instead of 80.
// After the split rounds, lane L holds the complete sum for index L>>1.
// Also zero-initializes g_ssum (fused init; keeps the graph at 4 kernels).
// ---------------------------------------------------------------------------
__global__ void __launch_bounds__(256) scores_kernel(
    const float* __restrict__ x,
    const float* __restrict__ aa,
    int n_nodes)
{
    const int lane  = threadIdx.x & 31;
    const int gwarp = (blockIdx.x * blockDim.x + threadIdx.x) >> 5;
    const int nwarp = (gridDim.x * blockDim.x) >> 5;

    // Load aa into registers: areg[i] = row i of aa (i<8: src head i, i>=8: dst
    // head i-8), features [4*lane, 4*lane+4). 16 float4 = 64 registers.
    float4 areg[16];
    const float4* aa4 = reinterpret_cast<const float4*>(aa);
#pragma unroll
    for (int h = 0; h < HEADS; h++) {
        areg[h]         = __ldg(&aa4[h * 64 + lane]);        // a_src[h]
        areg[HEADS + h] = __ldg(&aa4[h * 64 + 32 + lane]);   // a_dst[h]
    }

    const float4* x4 = reinterpret_cast<const float4*>(x);

    for (int node = gwarp; node < n_nodes; node += nwarp) {
        float4 xv = __ldg(&x4[(size_t)node * 32 + lane]);

        float acc[16];
#pragma unroll
        for (int i = 0; i < 16; i++)
            acc[i] = xv.x * areg[i].x + xv.y * areg[i].y
                   + xv.z * areg[i].z + xv.w * areg[i].w;

        // Value-splitting reduction. At step (OFF, NV): lane keeps half of its
        // values (upper lanes keep the top half), trades away the other half.
        // give = acc[gb+i]; partner's give is exactly the partial for the value
        // we keep. Write order is safe: writes go to acc[0..NV), reads to
        // acc[kb+i] with kb+i >= i.
#define RSTEP(OFF, NV)                                                     \
        {                                                                  \
            const int kb = (lane & (OFF)) ? (NV) : 0;                      \
            const int gb = (NV) - kb;                                      \
            _Pragma("unroll")                                              \
            for (int i = 0; i < (NV); i++) {                               \
                float give = acc[gb + i];                                  \
                float recv = __shfl_xor_sync(0xffffffffu, give, (OFF));    \
                acc[i] = acc[kb + i] + recv;                               \
            }                                                              \
        }
        RSTEP(16, 8)
        RSTEP(8, 4)
        RSTEP(4, 2)
        RSTEP(2, 1)
#undef RSTEP
        // Now lane holds partial for index (lane>>1); partner is lane^1.
        float r = acc[0] + __shfl_xor_sync(0xffffffffu, acc[0], 1);

        if (!(lane & 1)) {
            g_sc[(size_t)node * 16 + (lane >> 1)] = r;      // 16 even lanes
        } else if (lane < 16) {
            g_ssum[(size_t)node * 8 + (lane >> 1)] = 0.0f;  // 8 odd lanes: init
        }
    }
}

// ---------------------------------------------------------------------------
// Per-edge score recompute: e = lrelu(s_src[r][h] + s_dst[c][h]); ex = exp(e).
// Identical sequence in sum & out kernels so numerator/denominator terms match.
// ---------------------------------------------------------------------------
__device__ __forceinline__ void edge_exp(int r, int c, float4& ex0, float4& ex1)
{
    const float4* sc4 = reinterpret_cast<const float4*>(g_sc);
    float4 a0 = __ldg(&sc4[(size_t)r * 4 + 0]);
    float4 a1 = __ldg(&sc4[(size_t)r * 4 + 1]);
    float4 b0 = __ldg(&sc4[(size_t)c * 4 + 2]);
    float4 b1 = __ldg(&sc4[(size_t)c * 4 + 3]);

    float e0x = a0.x + b0.x, e0y = a0.y + b0.y, e0z = a0.z + b0.z, e0w = a0.w + b0.w;
    float e1x = a1.x + b1.x, e1y = a1.y + b1.y, e1z = a1.z + b1.z, e1w = a1.w + b1.w;

    e0x = fmaxf(e0x, ALPHA_F * e0x); e0y = fmaxf(e0y, ALPHA_F * e0y);
    e0z = fmaxf(e0z, ALPHA_F * e0z); e0w = fmaxf(e0w, ALPHA_F * e0w);
    e1x = fmaxf(e1x, ALPHA_F * e1x); e1y = fmaxf(e1y, ALPHA_F * e1y);
    e1z = fmaxf(e1z, ALPHA_F * e1z); e1w = fmaxf(e1w, ALPHA_F * e1w);

    ex0 = make_float4(__expf(e0x), __expf(e0y), __expf(e0z), __expf(e0w));
    ex1 = make_float4(__expf(e1x), __expf(e1y), __expf(e1z), __expf(e1w));
}

// ---------------------------------------------------------------------------
// Kernel 2: segment-sum of exp(e) via vectorized L2-side reductions.
// ---------------------------------------------------------------------------
__global__ void __launch_bounds__(256) sum_kernel(
    const int* __restrict__ row,
    const int* __restrict__ col,
    int n_edges)
{
    int e = blockIdx.x * blockDim.x + threadIdx.x;
    if (e >= n_edges) return;
    int r = __ldg(row + e);
    int c = __ldg(col + e);

    float4 ex0, ex1;
    edge_exp(r, c, ex0, ex1);

    float* dst = g_ssum + (size_t)r * 8;
    asm volatile("red.global.add.v4.f32 [%0], {%1,%2,%3,%4};"
                 :: "l"(dst),     "f"(ex0.x), "f"(ex0.y), "f"(ex0.z), "f"(ex0.w)
                 : "memory");
    asm volatile("red.global.add.v4.f32 [%0], {%1,%2,%3,%4};"
                 :: "l"(dst + 4), "f"(ex1.x), "f"(ex1.y), "f"(ex1.z), "f"(ex1.w)
                 : "memory");
}

// ---------------------------------------------------------------------------
// Kernel 2.5: invert sums in place: g_ssum = 1/(g_ssum + EPS).
// ---------------------------------------------------------------------------
__global__ void __launch_bounds__(256) inv_kernel(int n4)  // n4 = N_NODES*8/4
{
    int i = blockIdx.x * blockDim.x + threadIdx.x;
    if (i >= n4) return;
    float4* p = reinterpret_cast<float4*>(g_ssum);
    float4 v = p[i];
    v.x = __frcp_rn(v.x + EPS_F);
    v.y = __frcp_rn(v.y + EPS_F);
    v.z = __frcp_rn(v.z + EPS_F);
    v.w = __frcp_rn(v.w + EPS_F);
    p[i] = v;
}

// ---------------------------------------------------------------------------
// Kernel 3: a[h][e] = exp(e) * inv_ssum[row][h], transposed (head-major) write.
// Each of the 8 stores is a fully coalesced 128B warp transaction.
// ---------------------------------------------------------------------------
__global__ void __launch_bounds__(256) out_kernel(
    const int* __restrict__ row,
    const int* __restrict__ col,
    float* __restrict__ out,
    int n_edges)
{
    int e = blockIdx.x * blockDim.x + threadIdx.x;
    if (e >= n_edges) return;
    int r = __ldg(row + e);
    int c = __ldg(col + e);

    float4 ex0, ex1;
    edge_exp(r, c, ex0, ex1);

    const float4* ss4 = reinterpret_cast<const float4*>(g_ssum);
    float4 s0 = __ldg(&ss4[(size_t)r * 2 + 0]);
    float4 s1 = __ldg(&ss4[(size_t)r * 2 + 1]);

    size_t E = (size_t)n_edges;
    out[0 * E + e] = ex0.x * s0.x;
    out[1 * E + e] = ex0.y * s0.y;
    out[2 * E + e] = ex0.z * s0.z;
    out[3 * E + e] = ex0.w * s0.w;
    out[4 * E + e] = ex1.x * s1.x;
    out[5 * E + e] = ex1.y * s1.y;
    out[6 * E + e] = ex1.z * s1.z;
    out[7 * E + e] = ex1.w * s1.w;
}

extern "C" void kernel_launch(void* const* d_in, const int* in_sizes, int n_in,
                              void* d_out, int out_size)
{
    const float* x   = (const float*)d_in[0];
    const int*   row = (const int*)  d_in[1];
    const int*   col = (const int*)  d_in[2];
    const float* aa  = (const float*)d_in[3];
    float* out = (float*)d_out;

    int n_nodes = in_sizes[0] / FDIM;   // 100000
    int n_edges = in_sizes[1];          // 1600000

    // K1: grid-stride, ~10 nodes per warp to amortize the aa register load.
    scores_kernel<<<1184, 256>>>(x, aa, n_nodes);

    // K2: segment-sum of exp
    sum_kernel<<<(n_edges + 255) / 256, 256>>>(row, col, n_edges);

    // K2.5: invert sums
    {
        int n4 = n_nodes * HEADS / 4;
        inv_kernel<<<(n4 + 255) / 256, 256>>>(n4);
    }

    // K3: normalize + transposed write
    out_kernel<<<(n_edges + 255) / 256, 256>>>(row, col, out, n_edges);
}